// round 2
// baseline (speedup 1.0000x reference)
#include <cuda_runtime.h>
#include <math.h>

// Problem constants
#define BB   64          // batch
#define SS   512         // sequence length
#define II   256         // input size
#define HH   512         // hidden size
#define KTOT (II + HH)   // 768  GEMM K
#define G4   (4 * HH)    // 2048 gate columns per direction

// Tiling
#define NT   8           // h-columns per block  -> 32 gate columns per block
#define KT   32          // K chunk
#define NBLK (HH / NT)   // 64 N-tiles per direction

// Persistent state (device globals; no allocation allowed)
__device__ float g_h[2][2][BB][HH];   // [dir][parity][b][k], double-buffered across steps
__device__ float g_c[2][BB][HH];      // [dir][b][k]
__device__ float g_hb[(size_t)BB * SS * HH];  // 0.5 * h_backward at logical time index

__global__ void zero_state_kernel() {
    int idx = blockIdx.x * blockDim.x + threadIdx.x;   // 131072 threads
    if (idx < 2 * 2 * BB * HH) ((float*)g_h)[idx] = 0.0f;
    if (idx < 2 * BB * HH)     ((float*)g_c)[idx] = 0.0f;
}

// One recurrence step, both directions.
// Block: 256 threads. blockIdx.x = N-tile (h-cols n0..n0+NT-1), blockIdx.y = dir.
// Computes gates[b][col] = bias[col] + sum_k [x|h][b][k] * W[k][col]
// for the 32 columns {gate*512 + n0 + j : gate<4, j<8}, then the LSTM pointwise.
__global__ void __launch_bounds__(256) lstm_step_kernel(
    const float* __restrict__ x,     // [B][S][I]
    const float* __restrict__ W_f,   // [768][2048]
    const float* __restrict__ b_f,   // [2048]
    const float* __restrict__ W_b,
    const float* __restrict__ b_b,
    float* __restrict__ out,         // [B][S][H] (forward halves)
    int t)
{
    const int dir = blockIdx.y;
    const float* __restrict__ Wm   = dir ? W_b : W_f;
    const float* __restrict__ bias = dir ? b_b : b_f;
    const int tx = dir ? (SS - 1 - t) : t;  // time index into x (and output slot)
    const int n0 = blockIdx.x * NT;
    const int p  = t & 1;                   // read parity of h

    __shared__ float As[KT][BB + 2];  // [k][m], padded (row stride 66 floats, 8B aligned)
    __shared__ float Bs[KT][32];      // [k][c]
    __shared__ float Gs[BB][33];      // gate tile, padded

    const int tid = threadIdx.x;
    const int tm  = tid & 31;   // m pair: rows tm*2, tm*2+1
    const int tn  = tid >> 5;   // col quad: cols tn*4 .. tn*4+3

    // accumulators, seeded with bias
    float acc[2][4];
#pragma unroll
    for (int ci = 0; ci < 4; ci++) {
        int c   = tn * 4 + ci;
        int col = (c >> 3) * HH + n0 + (c & 7);
        float bv = bias[col];
        acc[0][ci] = bv;
        acc[1][ci] = bv;
    }

    // A-load mapping: b = tid>>2, kq = (tid&3)*8, 8 consecutive k each
    const int a_b  = tid >> 2;
    const int a_kq = (tid & 3) * 8;
    // B-load mapping: c = tid&31, kk = tid>>5, 4 k-rows each
    const int b_c  = tid & 31;
    const int b_kk = tid >> 5;
    const int b_col = (b_c >> 3) * HH + n0 + (b_c & 7);

    const float* __restrict__ hrow = &g_h[dir][p][0][0];

#pragma unroll 1
    for (int k0 = 0; k0 < KTOT; k0 += KT) {
        // ---- load A chunk: [x | h] rows, transposed into As[k][b] ----
        {
            const float* src;
            if (k0 < II) {
                src = &x[((size_t)a_b * SS + tx) * II + (k0 + a_kq)];
            } else {
                src = &hrow[(size_t)a_b * HH + (k0 - II + a_kq)];
            }
            float4 v0 = *(const float4*)(src);
            float4 v1 = *(const float4*)(src + 4);
            As[a_kq + 0][a_b] = v0.x;  As[a_kq + 1][a_b] = v0.y;
            As[a_kq + 2][a_b] = v0.z;  As[a_kq + 3][a_b] = v0.w;
            As[a_kq + 4][a_b] = v1.x;  As[a_kq + 5][a_b] = v1.y;
            As[a_kq + 6][a_b] = v1.z;  As[a_kq + 7][a_b] = v1.w;
        }
        // ---- load B chunk: W rows k0..k0+31 for our 32 columns ----
#pragma unroll
        for (int j = 0; j < 4; j++) {
            int k = b_kk * 4 + j;
            Bs[k][b_c] = Wm[(size_t)(k0 + k) * G4 + b_col];
        }
        __syncthreads();

        // ---- FMA: 2m x 4n register tile over KT ----
#pragma unroll
        for (int k = 0; k < KT; k++) {
            float2 a  = *(const float2*)&As[k][tm * 2];
            float4 bv = *(const float4*)&Bs[k][tn * 4];
            acc[0][0] += a.x * bv.x;  acc[0][1] += a.x * bv.y;
            acc[0][2] += a.x * bv.z;  acc[0][3] += a.x * bv.w;
            acc[1][0] += a.y * bv.x;  acc[1][1] += a.y * bv.y;
            acc[1][2] += a.y * bv.z;  acc[1][3] += a.y * bv.w;
        }
        __syncthreads();
    }

    // ---- stage gates to smem so f/i/o/g for one column meet in one thread ----
#pragma unroll
    for (int mi = 0; mi < 2; mi++)
#pragma unroll
        for (int ci = 0; ci < 4; ci++)
            Gs[tm * 2 + mi][tn * 4 + ci] = acc[mi][ci];
    __syncthreads();

    // ---- pointwise LSTM update: 512 (b, j) elements, 2 per thread ----
#pragma unroll
    for (int r = 0; r < 2; r++) {
        int e = tid + r * 256;       // 0..511
        int b = e & 63;
        int j = e >> 6;              // 0..7
        float fg = Gs[b][0  + j];
        float ig = Gs[b][8  + j];
        float og = Gs[b][16 + j];
        float gg = Gs[b][24 + j];

        float fs = 1.0f / (1.0f + __expf(-fg));
        float is = 1.0f / (1.0f + __expf(-ig));
        float os = 1.0f / (1.0f + __expf(-og));

        int n = n0 + j;
        float cprev = g_c[dir][b][n];
        float cn = fs * cprev + is * tanhf(gg);
        float hn = os * tanhf(cn);

        g_c[dir][b][n] = cn;
        g_h[dir][1 - p][b][n] = hn;

        size_t oidx = ((size_t)b * SS + tx) * HH + n;
        if (dir == 0) out[oidx]  = 0.5f * hn;
        else          g_hb[oidx] = 0.5f * hn;
    }
}

// out = 0.5*hf + 0.5*hb  (both halves already scaled)
__global__ void combine_kernel(float* __restrict__ out) {
    size_t i = (size_t)blockIdx.x * blockDim.x + threadIdx.x;  // float4 index
    const size_t n4 = (size_t)BB * SS * HH / 4;
    if (i < n4) {
        float4 a = ((const float4*)out)[i];
        float4 b = ((const float4*)g_hb)[i];
        a.x += b.x; a.y += b.y; a.z += b.z; a.w += b.w;
        ((float4*)out)[i] = a;
    }
}

extern "C" void kernel_launch(void* const* d_in, const int* in_sizes, int n_in,
                              void* d_out, int out_size) {
    const float* x   = (const float*)d_in[0];
    const float* W_f = (const float*)d_in[1];
    const float* b_f = (const float*)d_in[2];
    const float* W_b = (const float*)d_in[3];
    const float* b_b = (const float*)d_in[4];
    float* out = (float*)d_out;

    zero_state_kernel<<<512, 256>>>();

    dim3 grid(NBLK, 2);
    for (int t = 0; t < SS; t++) {
        lstm_step_kernel<<<grid, 256>>>(x, W_f, b_f, W_b, b_b, out, t);
    }

    const int n4 = BB * SS * HH / 4;
    combine_kernel<<<(n4 + 255) / 256, 256>>>(out);
}

// round 4
// speedup vs baseline: 2.4334x; 2.4334x over previous
#include <cuda_runtime.h>
#include <cuda_bf16.h>
#include <cstdint>
#include <math.h>

#define BB 64
#define SS 512
#define II 256
#define HH 512
#define KTOT 768
#define G4 2048
#define KC 64
#define NCH 12                 // 768/64
#define NTILES 64              // 2048 permuted cols / 32

#define ASTRIDE_B 144          // padded row stride bytes (72 bf16)
#define ST_A 9216              // one 64x64 A tile (64*144)
#define ST_B 4608              // one 32x64 B tile (32*144)
#define ST_BYTES (2*ST_A + 2*ST_B)   // 27648 per stage
#define SMEM_DYN (2*ST_BYTES)        // 55296

// ---------------- persistent device state ----------------
__device__ float g_c[2 * BB * HH];
__device__ __align__(16) __nv_bfloat16 g_h_hi[2 * 2 * BB * HH];   // [dir][parity][b][n]
__device__ __align__(16) __nv_bfloat16 g_h_lo[2 * 2 * BB * HH];
__device__ __align__(16) __nv_bfloat16 g_x_hi[(size_t)BB * SS * II];
__device__ __align__(16) __nv_bfloat16 g_x_lo[(size_t)BB * SS * II];
__device__ __align__(16) __nv_bfloat16 g_wt_hi[(size_t)2 * G4 * KTOT];  // [dir][prow][k]
__device__ __align__(16) __nv_bfloat16 g_wt_lo[(size_t)2 * G4 * KTOT];
__device__ __align__(16) float g_bias_p[2 * G4];                  // permuted bias
__device__ float g_hb[(size_t)BB * SS * HH];

// ---------------- helpers ----------------
__device__ __forceinline__ uint32_t smem_u32(const void* p) {
    uint32_t a;
    asm("{ .reg .u64 t; cvta.to.shared.u64 t, %1; cvt.u32.u64 %0, t; }" : "=r"(a) : "l"(p));
    return a;
}
__device__ __forceinline__ void cp16(uint32_t dst, const void* src) {
    asm volatile("cp.async.cg.shared.global [%0], [%1], 16;" :: "r"(dst), "l"(src));
}
__device__ __forceinline__ void cp_commit() { asm volatile("cp.async.commit_group;"); }
__device__ __forceinline__ void cp_wait0()  { asm volatile("cp.async.wait_group 0;"); }
__device__ __forceinline__ void cp_wait1()  { asm volatile("cp.async.wait_group 1;"); }

__device__ __forceinline__ void ldm_x4(uint32_t* r, uint32_t addr) {
    asm volatile("ldmatrix.sync.aligned.m8n8.x4.shared.b16 {%0,%1,%2,%3}, [%4];"
                 : "=r"(r[0]), "=r"(r[1]), "=r"(r[2]), "=r"(r[3]) : "r"(addr));
}
__device__ __forceinline__ void ldm_x2(uint32_t* r, uint32_t addr) {
    asm volatile("ldmatrix.sync.aligned.m8n8.x2.shared.b16 {%0,%1}, [%2];"
                 : "=r"(r[0]), "=r"(r[1]) : "r"(addr));
}
__device__ __forceinline__ void mma16816(float* c, const uint32_t* a, const uint32_t* b) {
    asm volatile("mma.sync.aligned.m16n8k16.row.col.f32.bf16.bf16.f32 "
                 "{%0,%1,%2,%3}, {%4,%5,%6,%7}, {%8,%9}, {%0,%1,%2,%3};"
                 : "+f"(c[0]), "+f"(c[1]), "+f"(c[2]), "+f"(c[3])
                 : "r"(a[0]), "r"(a[1]), "r"(a[2]), "r"(a[3]), "r"(b[0]), "r"(b[1]));
}

// ---------------- prep kernels ----------------
__global__ void zero_state_kernel() {
    int idx = blockIdx.x * blockDim.x + threadIdx.x;  // 131072
    if (idx < 2 * 2 * BB * HH) {
        g_h_hi[idx] = __nv_bfloat16(0.f);
        g_h_lo[idx] = __nv_bfloat16(0.f);
    }
    if (idx < 2 * BB * HH) g_c[idx] = 0.0f;
}

__global__ void prep_x_kernel(const float* __restrict__ x) {
    size_t i = (size_t)blockIdx.x * blockDim.x + threadIdx.x;
    if (i >= (size_t)BB * SS * II) return;
    float v = x[i];
    __nv_bfloat16 h = __float2bfloat16_rn(v);
    g_x_hi[i] = h;
    g_x_lo[i] = __float2bfloat16_rn(v - __bfloat162float(h));
}

// W[k][gc] -> Wt[dir][prow = j*4+gate][k], gc = gate*512 + j
__global__ void prep_w_kernel(const float* __restrict__ W_f, const float* __restrict__ W_b) {
    int idx = blockIdx.x * blockDim.x + threadIdx.x;
    if (idx >= 2 * KTOT * G4) return;
    int dir = idx / (KTOT * G4);
    int rem = idx % (KTOT * G4);
    int k  = rem / G4;
    int gc = rem % G4;
    float w = (dir ? W_b : W_f)[rem];
    int gate = gc >> 9;
    int j    = gc & 511;
    int prow = j * 4 + gate;
    size_t d = ((size_t)dir * G4 + prow) * KTOT + k;
    __nv_bfloat16 h = __float2bfloat16_rn(w);
    g_wt_hi[d] = h;
    g_wt_lo[d] = __float2bfloat16_rn(w - __bfloat162float(h));
}

__global__ void prep_bias_kernel(const float* __restrict__ b_f, const float* __restrict__ b_b) {
    int idx = blockIdx.x * blockDim.x + threadIdx.x;
    if (idx >= 2 * G4) return;
    int dir = idx / G4;
    int gc  = idx % G4;
    int gate = gc >> 9, j = gc & 511;
    g_bias_p[dir * G4 + j * 4 + gate] = (dir ? b_b : b_f)[gc];
}

// ---------------- per-step stage loader ----------------
__device__ __forceinline__ void load_stage(uint32_t smb, int buf, int ch,
                                           int tid, int dir, int p, int tx, int n0) {
    uint32_t base = smb + buf * ST_BYTES;
    const int k0 = ch * KC;
    // A tiles: 64 rows (batch) x 64 bf16, hi + lo
#pragma unroll
    for (int i = 0; i < 2; i++) {
        int idx = tid + i * 256;          // 0..511
        int r = idx >> 3, q = idx & 7;
        uint32_t doff = r * ASTRIDE_B + q * 16;
        const __nv_bfloat16 *sh, *sl;
        if (k0 < II) {
            size_t so = ((size_t)r * SS + tx) * II + k0 + q * 8;
            sh = g_x_hi + so; sl = g_x_lo + so;
        } else {
            size_t so = ((size_t)(dir * 2 + p) * BB + r) * HH + (k0 - II) + q * 8;
            sh = g_h_hi + so; sl = g_h_lo + so;
        }
        cp16(base + doff, sh);
        cp16(base + ST_A + doff, sl);
    }
    // B tiles: 32 permuted weight rows x 64 bf16, hi + lo
    {
        int r = tid >> 3, q = tid & 7;    // 256 units exactly
        size_t so = ((size_t)dir * G4 + n0 + r) * KTOT + k0 + q * 8;
        uint32_t doff = r * ASTRIDE_B + q * 16;
        cp16(base + 2 * ST_A + doff, g_wt_hi + so);
        cp16(base + 2 * ST_A + ST_B + doff, g_wt_lo + so);
    }
    cp_commit();
}

// ---------------- per-step kernel ----------------
// grid (64 tiles, 2 dirs), 256 threads (8 warps, warp tile 16x16 of 64x32)
__global__ void __launch_bounds__(256, 1) lstm_step_mma(float* __restrict__ out, int t) {
    extern __shared__ __align__(16) char sm[];
    const int tid  = threadIdx.x;
    const int lane = tid & 31;
    const int wid  = tid >> 5;
    const int wm   = wid & 3;       // 4 M slices of 16 rows
    const int wn   = wid >> 2;      // 2 N slices of 16 cols
    const int tile = blockIdx.x;
    const int dir  = blockIdx.y;
    const int tx = dir ? (SS - 1 - t) : t;
    const int p  = t & 1;
    const int n0 = tile * 32;       // permuted weight-row base
    const int j0 = tile * 8;        // hidden-col base
    const uint32_t smb = smem_u32(sm);

    float acc[2][4];
#pragma unroll
    for (int nt = 0; nt < 2; nt++)
#pragma unroll
        for (int i = 0; i < 4; i++) acc[nt][i] = 0.0f;

    load_stage(smb, 0, 0, tid, dir, p, tx, n0);

#pragma unroll 1
    for (int ch = 0; ch < NCH; ch++) {
        if (ch + 1 < NCH) {
            load_stage(smb, (ch + 1) & 1, ch + 1, tid, dir, p, tx, n0);
            cp_wait1();
        } else {
            cp_wait0();
        }
        __syncthreads();

        const uint32_t Ab = smb + (ch & 1) * ST_BYTES;
        const uint32_t Bb = Ab + 2 * ST_A;
#pragma unroll
        for (int ks = 0; ks < 4; ks++) {
            uint32_t ah[4], al[4], bh[2][2], bl[2][2];
            uint32_t ad = Ab + (uint32_t)(wm * 16 + (lane & 15)) * ASTRIDE_B
                             + (uint32_t)(ks * 16 + (lane >> 4) * 8) * 2;
            ldm_x4(ah, ad);
            ldm_x4(al, ad + ST_A);
#pragma unroll
            for (int nt = 0; nt < 2; nt++) {
                uint32_t bd = Bb + (uint32_t)(wn * 16 + nt * 8 + (lane & 7)) * ASTRIDE_B
                                 + (uint32_t)(ks * 16 + ((lane >> 3) & 1) * 8) * 2;
                ldm_x2(bh[nt], bd);
                ldm_x2(bl[nt], bd + ST_B);
            }
#pragma unroll
            for (int nt = 0; nt < 2; nt++) {
                mma16816(acc[nt], ah, bh[nt]);
                mma16816(acc[nt], al, bh[nt]);
                mma16816(acc[nt], ah, bl[nt]);
            }
        }
        __syncthreads();
    }

    // ---- epilogue: gates to smem (cols permuted j*4+gate -> float4 per (b,j)) ----
    float* Gs = (float*)sm;   // [64][36]
#pragma unroll
    for (int nt = 0; nt < 2; nt++) {
        int row = wm * 16 + (lane >> 2);
        int col = wn * 16 + nt * 8 + 2 * (lane & 3);
        *(float2*)&Gs[row * 36 + col]       = make_float2(acc[nt][0], acc[nt][1]);
        *(float2*)&Gs[(row + 8) * 36 + col] = make_float2(acc[nt][2], acc[nt][3]);
    }
    __syncthreads();

    // ---- pointwise LSTM update: 512 (b, j) elems, 2 per thread ----
#pragma unroll
    for (int r2 = 0; r2 < 2; r2++) {
        int e = tid + r2 * 256;       // 0..511
        int b = e & 63;
        int jl = e >> 6;              // 0..7
        float4 g  = *(float4*)&Gs[b * 36 + jl * 4];
        float4 bi = *(const float4*)&g_bias_p[dir * G4 + (j0 + jl) * 4];
        float fg = g.x + bi.x;
        float ig = g.y + bi.y;
        float og = g.z + bi.z;
        float gg = g.w + bi.w;
        float fs = 1.0f / (1.0f + __expf(-fg));
        float is = 1.0f / (1.0f + __expf(-ig));
        float os = 1.0f / (1.0f + __expf(-og));
        int n = j0 + jl;
        float cprev = g_c[(dir * BB + b) * HH + n];
        float cn = fs * cprev + is * tanhf(gg);
        float hn = os * tanhf(cn);
        g_c[(dir * BB + b) * HH + n] = cn;
        size_t hidx = ((size_t)(dir * 2 + (1 - p)) * BB + b) * HH + n;
        __nv_bfloat16 hh = __float2bfloat16_rn(hn);
        g_h_hi[hidx] = hh;
        g_h_lo[hidx] = __float2bfloat16_rn(hn - __bfloat162float(hh));
        size_t oi = ((size_t)b * SS + tx) * HH + n;
        if (dir == 0) out[oi]  = 0.5f * hn;
        else          g_hb[oi] = 0.5f * hn;
    }
}

// out = 0.5*hf + 0.5*hb
__global__ void combine_kernel(float* __restrict__ out) {
    size_t i = (size_t)blockIdx.x * blockDim.x + threadIdx.x;
    const size_t n4 = (size_t)BB * SS * HH / 4;
    if (i < n4) {
        float4 a = ((const float4*)out)[i];
        float4 b = ((const float4*)g_hb)[i];
        a.x += b.x; a.y += b.y; a.z += b.z; a.w += b.w;
        ((float4*)out)[i] = a;
    }
}

extern "C" void kernel_launch(void* const* d_in, const int* in_sizes, int n_in,
                              void* d_out, int out_size) {
    const float* x   = (const float*)d_in[0];
    const float* W_f = (const float*)d_in[1];
    const float* b_f = (const float*)d_in[2];
    const float* W_b = (const float*)d_in[3];
    const float* b_b = (const float*)d_in[4];
    float* out = (float*)d_out;

    cudaFuncSetAttribute((const void*)lstm_step_mma,
                         cudaFuncAttributeMaxDynamicSharedMemorySize, SMEM_DYN);

    zero_state_kernel<<<512, 256>>>();
    {
        size_t nx = (size_t)BB * SS * II;
        prep_x_kernel<<<(unsigned)((nx + 255) / 256), 256>>>(x);
    }
    prep_w_kernel<<<(2 * KTOT * G4 + 255) / 256, 256>>>(W_f, W_b);
    prep_bias_kernel<<<(2 * G4 + 255) / 256, 256>>>(b_f, b_b);

    dim3 grid(NTILES, 2);
    for (int t = 0; t < SS; t++) {
        lstm_step_mma<<<grid, 256, SMEM_DYN>>>(out, t);
    }

    const int n4 = BB * SS * HH / 4;
    combine_kernel<<<(n4 + 255) / 256, 256>>>(out);
}